// round 1
// baseline (speedup 1.0000x reference)
#include <cuda_runtime.h>
#include <cuda_bf16.h>
#include <math.h>

// ---------------------------------------------------------------------------
// Encoder layer: B=2, S=2048, M=1024, H=16 heads, D=64, FFN=2048, fp32
// ---------------------------------------------------------------------------

#define B_DIM 2
#define S_DIM 2048
#define M_DIM 1024
#define NHEAD 16
#define HDIM 64
#define FFN_H 2048
#define TOK (B_DIM * S_DIM)          // 4096 tokens
#define QKV_N (3 * M_DIM)            // 3072
#define NEGV -1e9f

// ------------------------- scratch (static device) -------------------------
__device__ float g_Wqkv[M_DIM * QKV_N];        // packed [K=1024, N=3072]
__device__ float g_bqkv[QKV_N];
__device__ float g_qkv[TOK * QKV_N];           // [token, 3072] (q|k|v), +bias
__device__ float g_ctx[TOK * M_DIM];           // attention output (heads concat)
__device__ float g_attnproj[TOK * M_DIM];      // ctx @ Wo + bo
__device__ float g_y[TOK * M_DIM];             // LN1(attnproj + x)
__device__ float g_ffh[TOK * FFN_H];           // relu(y@W1+b1)
__device__ float g_ffo[TOK * M_DIM];           // ffh@W2+b2

// ------------------------- weight repack -----------------------------------
// Wq/Wk/Wv: [H, M, D] -> packed [k, n] with n = which*1024 + h*64 + d
__global__ void pack_qkv_kernel(const float* __restrict__ Wq,
                                const float* __restrict__ Wk,
                                const float* __restrict__ Wv,
                                const float* __restrict__ bq,
                                const float* __restrict__ bk,
                                const float* __restrict__ bv) {
    int idx = blockIdx.x * blockDim.x + threadIdx.x;
    if (idx < M_DIM * QKV_N) {
        int n = idx % QKV_N;
        int k = idx / QKV_N;
        int which = n / M_DIM;
        int hd = n % M_DIM;
        int h = hd / HDIM, d = hd % HDIM;
        const float* W = (which == 0) ? Wq : (which == 1) ? Wk : Wv;
        g_Wqkv[idx] = W[((size_t)h * M_DIM + k) * HDIM + d];
    }
    if (idx < QKV_N) {
        int which = idx / M_DIM;
        int hd = idx % M_DIM;
        const float* bb = (which == 0) ? bq : (which == 1) ? bk : bv;
        g_bqkv[idx] = bb[hd];
    }
}

// ------------------------- register-tiled GEMM -----------------------------
// C[M,N] = A[M,K] @ B[K,N] + bias[N], optional ReLU.
// Block tile 128x128, K-step 16, 256 threads, 8x8 per thread.
// Requires M%128==0, N%128==0, K%16==0 (all shapes here satisfy this).
template <bool RELU>
__global__ __launch_bounds__(256)
void gemm_kernel(const float* __restrict__ A, const float* __restrict__ Bm,
                 const float* __restrict__ bias, float* __restrict__ C,
                 int M, int N, int K) {
    __shared__ float As[16][132];
    __shared__ float Bs[16][132];

    const int tid = threadIdx.x;
    const int tx = tid & 15;        // 0..15 -> N dir
    const int ty = tid >> 4;        // 0..15 -> M dir
    const int row0 = blockIdx.y * 128;
    const int col0 = blockIdx.x * 128;

    float acc[8][8];
#pragma unroll
    for (int i = 0; i < 8; i++)
#pragma unroll
        for (int j = 0; j < 8; j++) acc[i][j] = 0.f;

    for (int k0 = 0; k0 < K; k0 += 16) {
        // A tile: 128 rows x 16 k -> As[k][m]
#pragma unroll
        for (int it = 0; it < 2; it++) {
            int idx = tid + it * 256;          // 0..511
            int r = idx >> 2, c4 = idx & 3;
            float4 v = *(const float4*)&A[(size_t)(row0 + r) * K + k0 + c4 * 4];
            As[c4 * 4 + 0][r] = v.x;
            As[c4 * 4 + 1][r] = v.y;
            As[c4 * 4 + 2][r] = v.z;
            As[c4 * 4 + 3][r] = v.w;
        }
        // B tile: 16 k x 128 n -> Bs[k][n]
#pragma unroll
        for (int it = 0; it < 2; it++) {
            int idx = tid + it * 256;          // 0..511
            int r = idx >> 5, c4 = idx & 31;
            float4 v = *(const float4*)&Bm[(size_t)(k0 + r) * N + col0 + c4 * 4];
            *(float4*)&Bs[r][c4 * 4] = v;
        }
        __syncthreads();

#pragma unroll
        for (int kk = 0; kk < 16; kk++) {
            float a[8], b[8];
#pragma unroll
            for (int i = 0; i < 8; i++) a[i] = As[kk][ty * 8 + i];
#pragma unroll
            for (int j = 0; j < 8; j++) b[j] = Bs[kk][tx * 8 + j];
#pragma unroll
            for (int i = 0; i < 8; i++)
#pragma unroll
                for (int j = 0; j < 8; j++) acc[i][j] += a[i] * b[j];
        }
        __syncthreads();
    }

#pragma unroll
    for (int i = 0; i < 8; i++) {
        int r = row0 + ty * 8 + i;
#pragma unroll
        for (int j = 0; j < 8; j++) {
            int c = col0 + tx * 8 + j;
            float v = acc[i][j] + bias[c];
            if (RELU) v = fmaxf(v, 0.f);
            C[(size_t)r * N + c] = v;
        }
    }
}

// ------------------------- flash attention ---------------------------------
// grid: (S/128, B*H), 128 threads; each thread owns one query row.
__global__ __launch_bounds__(128)
void attn_kernel(const float* __restrict__ qkv, const int* __restrict__ mask,
                 float* __restrict__ ctx) {
    __shared__ float Ks[64][68];
    __shared__ float Vs[64][68];
    __shared__ float Ms[64];

    const int bh = blockIdx.y;
    const int b = bh / NHEAD, h = bh % NHEAD;
    const int q0 = blockIdx.x * 128;
    const int tid = threadIdx.x;
    const int qi = q0 + tid;

    const float* qbase = qkv + (size_t)(b * S_DIM + qi) * QKV_N + h * HDIM;
    float q[HDIM];
#pragma unroll
    for (int i = 0; i < 16; i++) {
        float4 v = *(const float4*)(qbase + i * 4);
        q[i * 4 + 0] = v.x; q[i * 4 + 1] = v.y;
        q[i * 4 + 2] = v.z; q[i * 4 + 3] = v.w;
    }

    float o[HDIM];
#pragma unroll
    for (int d = 0; d < HDIM; d++) o[d] = 0.f;
    float mval = -INFINITY, lsum = 0.f;

    for (int kt = 0; kt < S_DIM; kt += 64) {
        __syncthreads();
        // load K/V tiles (64 keys x 64 dims)
#pragma unroll
        for (int it = 0; it < 8; it++) {
            int idx = tid + it * 128;          // 0..1023
            int r = idx >> 4, c4 = idx & 15;
            const float* kb = qkv + (size_t)(b * S_DIM + kt + r) * QKV_N
                              + M_DIM + h * HDIM + c4 * 4;
            *(float4*)&Ks[r][c4 * 4] = *(const float4*)kb;
            *(float4*)&Vs[r][c4 * 4] = *(const float4*)(kb + M_DIM);
        }
        if (tid < 64)
            Ms[tid] = mask[b * S_DIM + kt + tid] ? 0.f : NEGV;
        __syncthreads();

#pragma unroll 1
        for (int j0 = 0; j0 < 64; j0 += 16) {
            float s[16];
#pragma unroll
            for (int j = 0; j < 16; j++) {
                float a = 0.f;
#pragma unroll
                for (int d = 0; d < HDIM; d++) a += q[d] * Ks[j0 + j][d];
                s[j] = a * 0.125f + Ms[j0 + j];
            }
            float tm = mval;
#pragma unroll
            for (int j = 0; j < 16; j++) tm = fmaxf(tm, s[j]);
            float scale = __expf(mval - tm);
            lsum *= scale;
#pragma unroll
            for (int d = 0; d < HDIM; d++) o[d] *= scale;
#pragma unroll
            for (int j = 0; j < 16; j++) {
                float p = __expf(s[j] - tm);
                lsum += p;
#pragma unroll
                for (int d = 0; d < HDIM; d++) o[d] += p * Vs[j0 + j][d];
            }
            mval = tm;
        }
    }

    float inv = 1.f / lsum;
    float* cb = ctx + (size_t)(b * S_DIM + qi) * M_DIM + h * HDIM;
#pragma unroll
    for (int d = 0; d < HDIM; d++) cb[d] = o[d] * inv;
}

// ------------------------- residual + layernorm ----------------------------
// out[row] = LN(A[row] + R[row]) * g + be ; row len 1024, 256 threads (4/thr)
__global__ __launch_bounds__(256)
void ln_kernel(const float* __restrict__ A, const float* __restrict__ R,
               const float* __restrict__ g, const float* __restrict__ be,
               float* __restrict__ out) {
    __shared__ float red[8];
    __shared__ float bcast;
    const int row = blockIdx.x;
    const int tid = threadIdx.x;

    float4 a = ((const float4*)(A + (size_t)row * M_DIM))[tid];
    float4 r = ((const float4*)(R + (size_t)row * M_DIM))[tid];
    float v0 = a.x + r.x, v1 = a.y + r.y, v2 = a.z + r.z, v3 = a.w + r.w;

    float s = v0 + v1 + v2 + v3;
#pragma unroll
    for (int off = 16; off; off >>= 1) s += __shfl_xor_sync(0xffffffffu, s, off);
    if ((tid & 31) == 0) red[tid >> 5] = s;
    __syncthreads();
    if (tid == 0) {
        float t = 0.f;
#pragma unroll
        for (int i = 0; i < 8; i++) t += red[i];
        bcast = t * (1.f / M_DIM);
    }
    __syncthreads();
    const float mu = bcast;

    float d0 = v0 - mu, d1 = v1 - mu, d2 = v2 - mu, d3 = v3 - mu;
    float s2 = d0 * d0 + d1 * d1 + d2 * d2 + d3 * d3;
#pragma unroll
    for (int off = 16; off; off >>= 1) s2 += __shfl_xor_sync(0xffffffffu, s2, off);
    __syncthreads();                       // protect red[] reuse
    if ((tid & 31) == 0) red[tid >> 5] = s2;
    __syncthreads();
    if (tid == 0) {
        float t = 0.f;
#pragma unroll
        for (int i = 0; i < 8; i++) t += red[i];
        bcast = rsqrtf(t * (1.f / M_DIM) + 1e-5f);
    }
    __syncthreads();
    const float rstd = bcast;

    float4 gg = ((const float4*)g)[tid];
    float4 bb = ((const float4*)be)[tid];
    float4 o;
    o.x = d0 * rstd * gg.x + bb.x;
    o.y = d1 * rstd * gg.y + bb.y;
    o.z = d2 * rstd * gg.z + bb.z;
    o.w = d3 * rstd * gg.w + bb.w;
    ((float4*)(out + (size_t)row * M_DIM))[tid] = o;
}

// ---------------------------------------------------------------------------
extern "C" void kernel_launch(void* const* d_in, const int* in_sizes, int n_in,
                              void* d_out, int out_size) {
    const float* x     = (const float*)d_in[0];
    const int*   amask = (const int*)  d_in[1];
    const float* Wq    = (const float*)d_in[2];
    const float* bq    = (const float*)d_in[3];
    const float* Wk    = (const float*)d_in[4];
    const float* bk    = (const float*)d_in[5];
    const float* Wv    = (const float*)d_in[6];
    const float* bv    = (const float*)d_in[7];
    const float* Wo    = (const float*)d_in[8];
    const float* bo    = (const float*)d_in[9];
    const float* g1    = (const float*)d_in[10];
    const float* b1    = (const float*)d_in[11];
    const float* W1    = (const float*)d_in[12];
    const float* bias1 = (const float*)d_in[13];
    const float* W2    = (const float*)d_in[14];
    const float* bias2 = (const float*)d_in[15];
    const float* g2    = (const float*)d_in[16];
    const float* b2    = (const float*)d_in[17];
    float* out = (float*)d_out;

    float *Wqkv, *bqkv, *qkv, *ctx, *attnproj, *y, *ffh, *ffo;
    cudaGetSymbolAddress((void**)&Wqkv,     g_Wqkv);
    cudaGetSymbolAddress((void**)&bqkv,     g_bqkv);
    cudaGetSymbolAddress((void**)&qkv,      g_qkv);
    cudaGetSymbolAddress((void**)&ctx,      g_ctx);
    cudaGetSymbolAddress((void**)&attnproj, g_attnproj);
    cudaGetSymbolAddress((void**)&y,        g_y);
    cudaGetSymbolAddress((void**)&ffh,      g_ffh);
    cudaGetSymbolAddress((void**)&ffo,      g_ffo);

    // 1) pack per-head QKV weights into one [1024, 3072] matrix (+bias)
    pack_qkv_kernel<<<(M_DIM * QKV_N + 255) / 256, 256>>>(Wq, Wk, Wv, bq, bk, bv);

    // 2) fused QKV projection: [4096,1024] @ [1024,3072]
    {
        dim3 grid(QKV_N / 128, TOK / 128);
        gemm_kernel<false><<<grid, 256>>>(x, Wqkv, bqkv, qkv, TOK, QKV_N, M_DIM);
    }

    // 3) attention (flash-style, fp32)
    {
        dim3 grid(S_DIM / 128, B_DIM * NHEAD);
        attn_kernel<<<grid, 128>>>(qkv, amask, ctx);
    }

    // 4) output projection: ctx @ Wo + bo
    {
        dim3 grid(M_DIM / 128, TOK / 128);
        gemm_kernel<false><<<grid, 256>>>(ctx, Wo, bo, attnproj, TOK, M_DIM, M_DIM);
    }

    // 5) y = LN(attnproj + x)
    ln_kernel<<<TOK, 256>>>(attnproj, x, g1, b1, y);

    // 6) ffh = relu(y @ W1 + bias1)
    {
        dim3 grid(FFN_H / 128, TOK / 128);
        gemm_kernel<true><<<grid, 256>>>(y, W1, bias1, ffh, TOK, FFN_H, M_DIM);
    }

    // 7) ffo = ffh @ W2 + bias2
    {
        dim3 grid(M_DIM / 128, TOK / 128);
        gemm_kernel<false><<<grid, 256>>>(ffh, W2, bias2, ffo, TOK, M_DIM, FFN_H);
    }

    // 8) out = LN(y + ffo)
    ln_kernel<<<TOK, 256>>>(ffo, y, g2, b2, out);
}

// round 4
// speedup vs baseline: 3.1249x; 3.1249x over previous
#include <cuda_runtime.h>
#include <math.h>

#define B_DIM 2
#define S_DIM 2048
#define M_DIM 1024
#define NHEAD 16
#define HDIM 64
#define FFN_H 2048
#define TOK (B_DIM * S_DIM)          // 4096
#define QKV_N (3 * M_DIM)            // 3072
#define NEGV -1e9f

// ------------------------- scratch (static device) -------------------------
__device__ float g_Wqkv[M_DIM * QKV_N];
__device__ float g_bqkv[QKV_N];
__device__ float g_qkv[TOK * QKV_N];
__device__ float g_ctx[TOK * M_DIM];
__device__ float g_attnproj[TOK * M_DIM];
__device__ float g_y[TOK * M_DIM];
__device__ float g_ffh[TOK * FFN_H];
__device__ float g_ffo[TOK * M_DIM];

// ------------------------- tf32 helpers ------------------------------------
__device__ __forceinline__ float tf32r(float x) {
    unsigned r; asm("cvt.rna.tf32.f32 %0, %1;" : "=r"(r) : "f"(x));
    return __uint_as_float(r);
}
// D = A(16x8,row) * B(8x8,col) + D, tf32 inputs, fp32 accum
__device__ __forceinline__ void mma8(float* c, const unsigned* a, const unsigned* b) {
    asm volatile(
        "mma.sync.aligned.m16n8k8.row.col.f32.tf32.tf32.f32 "
        "{%0,%1,%2,%3},{%4,%5,%6,%7},{%8,%9},{%0,%1,%2,%3};"
        : "+f"(c[0]), "+f"(c[1]), "+f"(c[2]), "+f"(c[3])
        : "r"(a[0]), "r"(a[1]), "r"(a[2]), "r"(a[3]), "r"(b[0]), "r"(b[1]));
}

// ------------------------- weight repack -----------------------------------
__global__ void pack_qkv_kernel(const float* __restrict__ Wq,
                                const float* __restrict__ Wk,
                                const float* __restrict__ Wv,
                                const float* __restrict__ bq,
                                const float* __restrict__ bk,
                                const float* __restrict__ bv) {
    int idx = blockIdx.x * blockDim.x + threadIdx.x;
    if (idx < M_DIM * QKV_N) {
        int n = idx % QKV_N;
        int k = idx / QKV_N;
        int which = n / M_DIM;
        int hd = n % M_DIM;
        int h = hd / HDIM, d = hd % HDIM;
        const float* W = (which == 0) ? Wq : (which == 1) ? Wk : Wv;
        g_Wqkv[idx] = W[((size_t)h * M_DIM + k) * HDIM + d];
    }
    if (idx < QKV_N) {
        int which = idx / M_DIM;
        int hd = idx % M_DIM;
        const float* bb = (which == 0) ? bq : (which == 1) ? bk : bv;
        g_bqkv[idx] = bb[hd];
    }
}

// ------------------------- tf32 tensor-core GEMM ---------------------------
// C[M,N] = A[M,K]@B[K,N] + bias, optional ReLU. Tile 128x128, K-step 16,
// 256 thr = 8 warps (2x4), warp tile 64x32, double-buffered SMEM.
template <bool RELU>
__global__ __launch_bounds__(256)
void gemm_tc(const float* __restrict__ A, const float* __restrict__ Bm,
             const float* __restrict__ bias, float* __restrict__ C,
             int M, int N, int K) {
    __shared__ float As[2][128][20];   // [m][k] pad->conflict-free A frags
    __shared__ float Bs[2][16][136];   // [k][n] pad->conflict-free B frags

    const int tid = threadIdx.x, lane = tid & 31, w = tid >> 5;
    const int wm = w >> 2, wn = w & 3;
    const int g = lane >> 2, tg = lane & 3;
    const int row0 = blockIdx.y * 128, col0 = blockIdx.x * 128;

    const int ar = tid >> 2, ac = (tid & 3) * 4;     // A ldg: rows ar, ar+64
    const int br = tid >> 5, bc = (tid & 31) * 4;    // B ldg: rows br, br+8

    float4 stA[2], stB[2];
    float acc[4][4][4];
#pragma unroll
    for (int i = 0; i < 4; i++)
#pragma unroll
        for (int j = 0; j < 4; j++)
#pragma unroll
            for (int q = 0; q < 4; q++) acc[i][j][q] = 0.f;

    const int nk = K >> 4;

    // prologue: load + store stage 0
    {
        const float* Ap = A + (size_t)(row0 + ar) * K + ac;
        stA[0] = *(const float4*)Ap;
        stA[1] = *(const float4*)(Ap + (size_t)64 * K);
        const float* Bp = Bm + (size_t)br * N + col0 + bc;
        stB[0] = *(const float4*)Bp;
        stB[1] = *(const float4*)(Bp + (size_t)8 * N);
#pragma unroll
        for (int i = 0; i < 2; i++) {
            float4 v = stA[i];
            float4 rv = make_float4(tf32r(v.x), tf32r(v.y), tf32r(v.z), tf32r(v.w));
            *(float4*)&As[0][ar + i * 64][ac] = rv;
            v = stB[i];
            rv = make_float4(tf32r(v.x), tf32r(v.y), tf32r(v.z), tf32r(v.w));
            *(float4*)&Bs[0][br + i * 8][bc] = rv;
        }
    }
    __syncthreads();

    for (int kt = 0; kt < nk; kt++) {
        const int cur = kt & 1;
        if (kt + 1 < nk) {
            const int k0 = (kt + 1) << 4;
            const float* Ap = A + (size_t)(row0 + ar) * K + k0 + ac;
            stA[0] = *(const float4*)Ap;
            stA[1] = *(const float4*)(Ap + (size_t)64 * K);
            const float* Bp = Bm + (size_t)(k0 + br) * N + col0 + bc;
            stB[0] = *(const float4*)Bp;
            stB[1] = *(const float4*)(Bp + (size_t)8 * N);
        }

#pragma unroll
        for (int fk = 0; fk < 2; fk++) {
            unsigned af[4][4];
#pragma unroll
            for (int mi = 0; mi < 4; mi++) {
                const float* ap = &As[cur][wm * 64 + mi * 16][fk * 8];
                af[mi][0] = __float_as_uint(ap[g * 20 + tg]);
                af[mi][1] = __float_as_uint(ap[(g + 8) * 20 + tg]);
                af[mi][2] = __float_as_uint(ap[g * 20 + tg + 4]);
                af[mi][3] = __float_as_uint(ap[(g + 8) * 20 + tg + 4]);
            }
#pragma unroll
            for (int ni = 0; ni < 4; ni++) {
                unsigned bf[2];
                const int ncol = wn * 32 + ni * 8 + g;
                bf[0] = __float_as_uint(Bs[cur][fk * 8 + tg][ncol]);
                bf[1] = __float_as_uint(Bs[cur][fk * 8 + tg + 4][ncol]);
#pragma unroll
                for (int mi = 0; mi < 4; mi++) mma8(acc[mi][ni], af[mi], bf);
            }
        }

        if (kt + 1 < nk) {
            const int nxt = (kt + 1) & 1;
#pragma unroll
            for (int i = 0; i < 2; i++) {
                float4 v = stA[i];
                float4 rv = make_float4(tf32r(v.x), tf32r(v.y), tf32r(v.z), tf32r(v.w));
                *(float4*)&As[nxt][ar + i * 64][ac] = rv;
                v = stB[i];
                rv = make_float4(tf32r(v.x), tf32r(v.y), tf32r(v.z), tf32r(v.w));
                *(float4*)&Bs[nxt][br + i * 8][bc] = rv;
            }
        }
        __syncthreads();
    }

    // epilogue
#pragma unroll
    for (int mi = 0; mi < 4; mi++) {
        const int r = row0 + wm * 64 + mi * 16 + g;
#pragma unroll
        for (int ni = 0; ni < 4; ni++) {
            const int c = col0 + wn * 32 + ni * 8 + 2 * tg;
            const float b0 = bias[c], b1 = bias[c + 1];
            float v0 = acc[mi][ni][0] + b0, v1 = acc[mi][ni][1] + b1;
            float v2 = acc[mi][ni][2] + b0, v3 = acc[mi][ni][3] + b1;
            if (RELU) {
                v0 = fmaxf(v0, 0.f); v1 = fmaxf(v1, 0.f);
                v2 = fmaxf(v2, 0.f); v3 = fmaxf(v3, 0.f);
            }
            *(float2*)&C[(size_t)r * N + c] = make_float2(v0, v1);
            *(float2*)&C[(size_t)(r + 8) * N + c] = make_float2(v2, v3);
        }
    }
}

// ------------------------- tf32 flash attention ----------------------------
// grid (S/128, B*H), 256 thr = 8 warps; warp = 16 queries; key tile 64.
__global__ __launch_bounds__(256)
void attn_tc(const float* __restrict__ qkv, const int* __restrict__ mask,
             float* __restrict__ ctx) {
    extern __shared__ float sm[];
    float* Ks  = sm;                       // [64][68]
    float* Vs  = sm + 64 * 68;             // [64][68]
    float* Pw0 = sm + 2 * 64 * 68;         // [8][16][68]
    float* Ms  = Pw0 + 8 * 16 * 68;        // [64]

    const int tid = threadIdx.x, lane = tid & 31, w = tid >> 5;
    const int g = lane >> 2, tg = lane & 3;
    const int bh = blockIdx.y, b = bh >> 4, h = bh & 15;
    const int qw = blockIdx.x * 128 + w * 16;
    float* Pw = Pw0 + w * 16 * 68;

    // Q fragments (registers), pre-scaled by 1/sqrt(64)
    unsigned qf[8][4];
    {
        const float* qb = qkv + (size_t)(b * S_DIM + qw) * QKV_N + h * HDIM;
#pragma unroll
        for (int fk = 0; fk < 8; fk++) {
            qf[fk][0] = __float_as_uint(tf32r(qb[(size_t)g * QKV_N + fk * 8 + tg] * 0.125f));
            qf[fk][1] = __float_as_uint(tf32r(qb[(size_t)(g + 8) * QKV_N + fk * 8 + tg] * 0.125f));
            qf[fk][2] = __float_as_uint(tf32r(qb[(size_t)g * QKV_N + fk * 8 + tg + 4] * 0.125f));
            qf[fk][3] = __float_as_uint(tf32r(qb[(size_t)(g + 8) * QKV_N + fk * 8 + tg + 4] * 0.125f));
        }
    }

    float of[8][4];
#pragma unroll
    for (int i = 0; i < 8; i++) { of[i][0] = of[i][1] = of[i][2] = of[i][3] = 0.f; }
    float m0 = -INFINITY, m1 = -INFINITY, l0 = 0.f, l1 = 0.f;

    const int kr = tid >> 4, kc = (tid & 15) * 4;

    for (int kt = 0; kt < S_DIM; kt += 64) {
        __syncthreads();
#pragma unroll
        for (int i = 0; i < 4; i++) {
            const int r = kr + i * 16;
            const float* kb = qkv + (size_t)(b * S_DIM + kt + r) * QKV_N + M_DIM + h * HDIM + kc;
            float4 kv = *(const float4*)kb;
            float4 vv = *(const float4*)(kb + M_DIM);
            float* kd = &Ks[r * 68 + kc];
            kd[0] = tf32r(kv.x); kd[1] = tf32r(kv.y);
            kd[2] = tf32r(kv.z); kd[3] = tf32r(kv.w);
            float* vd = &Vs[r * 68 + kc];
            vd[0] = tf32r(vv.x); vd[1] = tf32r(vv.y);
            vd[2] = tf32r(vv.z); vd[3] = tf32r(vv.w);
        }
        if (tid < 64) Ms[tid] = mask[b * S_DIM + kt + tid] ? 0.f : NEGV;
        __syncthreads();

        // S = Q * K^T  (16 x 64 per warp)
        float s[8][4];
#pragma unroll
        for (int fn = 0; fn < 8; fn++) { s[fn][0] = s[fn][1] = s[fn][2] = s[fn][3] = 0.f; }
#pragma unroll
        for (int fk = 0; fk < 8; fk++) {
#pragma unroll
            for (int fn = 0; fn < 8; fn++) {
                unsigned bf[2];
                bf[0] = __float_as_uint(Ks[(fn * 8 + g) * 68 + fk * 8 + tg]);
                bf[1] = __float_as_uint(Ks[(fn * 8 + g) * 68 + fk * 8 + tg + 4]);
                mma8(s[fn], qf[fk], bf);
            }
        }

        // mask + online softmax (rows g and g+8)
        float mx0 = -INFINITY, mx1 = -INFINITY;
#pragma unroll
        for (int fn = 0; fn < 8; fn++) {
            const float mk0 = Ms[fn * 8 + 2 * tg], mk1 = Ms[fn * 8 + 2 * tg + 1];
            s[fn][0] += mk0; s[fn][1] += mk1;
            s[fn][2] += mk0; s[fn][3] += mk1;
            mx0 = fmaxf(mx0, fmaxf(s[fn][0], s[fn][1]));
            mx1 = fmaxf(mx1, fmaxf(s[fn][2], s[fn][3]));
        }
        mx0 = fmaxf(mx0, __shfl_xor_sync(0xffffffffu, mx0, 1));
        mx0 = fmaxf(mx0, __shfl_xor_sync(0xffffffffu, mx0, 2));
        mx1 = fmaxf(mx1, __shfl_xor_sync(0xffffffffu, mx1, 1));
        mx1 = fmaxf(mx1, __shfl_xor_sync(0xffffffffu, mx1, 2));
        const float nm0 = fmaxf(m0, mx0), nm1 = fmaxf(m1, mx1);
        const float a0 = __expf(m0 - nm0), a1 = __expf(m1 - nm1);
        m0 = nm0; m1 = nm1;
        l0 *= a0; l1 *= a1;
#pragma unroll
        for (int fn = 0; fn < 8; fn++) {
            of[fn][0] *= a0; of[fn][1] *= a0;
            of[fn][2] *= a1; of[fn][3] *= a1;
            float p0 = tf32r(__expf(s[fn][0] - m0));
            float p1 = tf32r(__expf(s[fn][1] - m0));
            float p2 = tf32r(__expf(s[fn][2] - m1));
            float p3 = tf32r(__expf(s[fn][3] - m1));
            l0 += p0 + p1; l1 += p2 + p3;
            *(float2*)&Pw[g * 68 + fn * 8 + 2 * tg] = make_float2(p0, p1);
            *(float2*)&Pw[(g + 8) * 68 + fn * 8 + 2 * tg] = make_float2(p2, p3);
        }
        __syncwarp();

        // O += P * V
#pragma unroll
        for (int fk = 0; fk < 8; fk++) {
            unsigned af[4];
            af[0] = __float_as_uint(Pw[g * 68 + fk * 8 + tg]);
            af[1] = __float_as_uint(Pw[(g + 8) * 68 + fk * 8 + tg]);
            af[2] = __float_as_uint(Pw[g * 68 + fk * 8 + tg + 4]);
            af[3] = __float_as_uint(Pw[(g + 8) * 68 + fk * 8 + tg + 4]);
#pragma unroll
            for (int fn = 0; fn < 8; fn++) {
                unsigned bf[2];
                bf[0] = __float_as_uint(Vs[(fk * 8 + tg) * 68 + fn * 8 + g]);
                bf[1] = __float_as_uint(Vs[(fk * 8 + tg + 4) * 68 + fn * 8 + g]);
                mma8(of[fn], af, bf);
            }
        }
        __syncwarp();
    }

    // FIX: l0/l1 are per-lane partial row sums (each lane covers 16 of 64
    // columns per tile). Reduce across the 4 lanes of the quad before
    // normalizing — m was reduced, l was not (this was the 3.3e-2 bug).
    l0 += __shfl_xor_sync(0xffffffffu, l0, 1);
    l0 += __shfl_xor_sync(0xffffffffu, l0, 2);
    l1 += __shfl_xor_sync(0xffffffffu, l1, 1);
    l1 += __shfl_xor_sync(0xffffffffu, l1, 2);

    const float i0 = 1.f / fmaxf(l0, 1e-30f), i1 = 1.f / fmaxf(l1, 1e-30f);
    float* cb = ctx + (size_t)(b * S_DIM + qw) * M_DIM + h * HDIM;
#pragma unroll
    for (int fn = 0; fn < 8; fn++) {
        *(float2*)&cb[(size_t)g * M_DIM + fn * 8 + 2 * tg] =
            make_float2(of[fn][0] * i0, of[fn][1] * i0);
        *(float2*)&cb[(size_t)(g + 8) * M_DIM + fn * 8 + 2 * tg] =
            make_float2(of[fn][2] * i1, of[fn][3] * i1);
    }
}

// ------------------------- residual + layernorm ----------------------------
__global__ __launch_bounds__(256)
void ln_kernel(const float* __restrict__ A, const float* __restrict__ R,
               const float* __restrict__ g, const float* __restrict__ be,
               float* __restrict__ out) {
    __shared__ float red[8];
    __shared__ float bcast;
    const int row = blockIdx.x;
    const int tid = threadIdx.x;

    float4 a = ((const float4*)(A + (size_t)row * M_DIM))[tid];
    float4 r = ((const float4*)(R + (size_t)row * M_DIM))[tid];
    float v0 = a.x + r.x, v1 = a.y + r.y, v2 = a.z + r.z, v3 = a.w + r.w;

    float s = v0 + v1 + v2 + v3;
#pragma unroll
    for (int off = 16; off; off >>= 1) s += __shfl_xor_sync(0xffffffffu, s, off);
    if ((tid & 31) == 0) red[tid >> 5] = s;
    __syncthreads();
    if (tid == 0) {
        float t = 0.f;
#pragma unroll
        for (int i = 0; i < 8; i++) t += red[i];
        bcast = t * (1.f / M_DIM);
    }
    __syncthreads();
    const float mu = bcast;

    float d0 = v0 - mu, d1 = v1 - mu, d2 = v2 - mu, d3 = v3 - mu;
    float s2 = d0 * d0 + d1 * d1 + d2 * d2 + d3 * d3;
#pragma unroll
    for (int off = 16; off; off >>= 1) s2 += __shfl_xor_sync(0xffffffffu, s2, off);
    __syncthreads();
    if ((tid & 31) == 0) red[tid >> 5] = s2;
    __syncthreads();
    if (tid == 0) {
        float t = 0.f;
#pragma unroll
        for (int i = 0; i < 8; i++) t += red[i];
        bcast = rsqrtf(t * (1.f / M_DIM) + 1e-5f);
    }
    __syncthreads();
    const float rstd = bcast;

    float4 gg = ((const float4*)g)[tid];
    float4 bb = ((const float4*)be)[tid];
    float4 o;
    o.x = d0 * rstd * gg.x + bb.x;
    o.y = d1 * rstd * gg.y + bb.y;
    o.z = d2 * rstd * gg.z + bb.z;
    o.w = d3 * rstd * gg.w + bb.w;
    ((float4*)(out + (size_t)row * M_DIM))[tid] = o;
}

// ---------------------------------------------------------------------------
extern "C" void kernel_launch(void* const* d_in, const int* in_sizes, int n_in,
                              void* d_out, int out_size) {
    const float* x     = (const float*)d_in[0];
    const int*   amask = (const int*)  d_in[1];
    const float* Wq    = (const float*)d_in[2];
    const float* bq    = (const float*)d_in[3];
    const float* Wk    = (const float*)d_in[4];
    const float* bk    = (const float*)d_in[5];
    const float* Wv    = (const float*)d_in[6];
    const float* bv    = (const float*)d_in[7];
    const float* Wo    = (const float*)d_in[8];
    const float* bo    = (const float*)d_in[9];
    const float* g1    = (const float*)d_in[10];
    const float* b1    = (const float*)d_in[11];
    const float* W1    = (const float*)d_in[12];
    const float* bias1 = (const float*)d_in[13];
    const float* W2    = (const float*)d_in[14];
    const float* bias2 = (const float*)d_in[15];
    const float* g2    = (const float*)d_in[16];
    const float* b2    = (const float*)d_in[17];
    float* out = (float*)d_out;

    float *Wqkv, *bqkv, *qkv, *ctx, *attnproj, *y, *ffh, *ffo;
    cudaGetSymbolAddress((void**)&Wqkv,     g_Wqkv);
    cudaGetSymbolAddress((void**)&bqkv,     g_bqkv);
    cudaGetSymbolAddress((void**)&qkv,      g_qkv);
    cudaGetSymbolAddress((void**)&ctx,      g_ctx);
    cudaGetSymbolAddress((void**)&attnproj, g_attnproj);
    cudaGetSymbolAddress((void**)&y,        g_y);
    cudaGetSymbolAddress((void**)&ffh,      g_ffh);
    cudaGetSymbolAddress((void**)&ffo,      g_ffo);

    const int attn_smem = (2 * 64 * 68 + 8 * 16 * 68 + 64) * sizeof(float);
    cudaFuncSetAttribute(attn_tc, cudaFuncAttributeMaxDynamicSharedMemorySize,
                         attn_smem);

    // 1) pack per-head QKV weights
    pack_qkv_kernel<<<(M_DIM * QKV_N + 255) / 256, 256>>>(Wq, Wk, Wv, bq, bk, bv);

    // 2) fused QKV projection
    {
        dim3 grid(QKV_N / 128, TOK / 128);
        gemm_tc<false><<<grid, 256>>>(x, Wqkv, bqkv, qkv, TOK, QKV_N, M_DIM);
    }

    // 3) attention
    {
        dim3 grid(S_DIM / 128, B_DIM * NHEAD);
        attn_tc<<<grid, 256, attn_smem>>>(qkv, amask, ctx);
    }

    // 4) output projection
    {
        dim3 grid(M_DIM / 128, TOK / 128);
        gemm_tc<false><<<grid, 256>>>(ctx, Wo, bo, attnproj, TOK, M_DIM, M_DIM);
    }

    // 5) y = LN(attnproj + x)
    ln_kernel<<<TOK, 256>>>(attnproj, x, g1, b1, y);

    // 6) ffh = relu(y @ W1 + bias1)
    {
        dim3 grid(FFN_H / 128, TOK / 128);
        gemm_tc<true><<<grid, 256>>>(y, W1, bias1, ffh, TOK, FFN_H, M_DIM);
    }

    // 7) ffo = ffh @ W2 + bias2
    {
        dim3 grid(M_DIM / 128, TOK / 128);
        gemm_tc<false><<<grid, 256>>>(ffh, W2, bias2, ffo, TOK, M_DIM, FFN_H);
    }

    // 8) out = LN(y + ffo)
    ln_kernel<<<TOK, 256>>>(ffo, y, g2, b2, out);
}